// round 6
// baseline (speedup 1.0000x reference)
#include <cuda_runtime.h>

#define N_TOK 16384
#define KCB   8192
#define DDIM  256
#define SS    132   // smem row stride (floats): mult of 4 for 16B alignment

// ---- output layout (float32, reference return order, flattened) ----
#define O_QUANT 0
#define O_LOSS  4194304
#define O_IDX   4194305
#define O_W     4210689
#define O_CS    6307841
#define O_EMAW  6316033

// ---- scratch (__device__ globals: no allocation allowed) ----
__device__ float              g_E2[KCB];     // sum(w_k^2), reference order
__device__ float              g_S[N_TOK];    // sum(x_i^2), reference order
__device__ unsigned long long g_best[N_TOK];
__device__ float              g_counts[KCB];
__device__ float              g_dw[KCB * DDIM];
__device__ float              g_lossAcc;
__device__ float              g_ncs[KCB];
__device__ float              g_n;

// ============================================================
// prep: zero scratch; S_i and E_k as STRICT sequential unfused
// fp32 sums (replicating XLA-CPU's non-reassociated reduce loop)
// ============================================================
__global__ void k_prep(const float* __restrict__ z, const float* __restrict__ w) {
    int tid = blockIdx.x * 256 + threadIdx.x;
    int T = gridDim.x * 256;
    for (int i = tid; i < KCB * DDIM; i += T) g_dw[i] = 0.0f;
    if (tid < N_TOK) g_best[tid] = 0xFFFFFFFFFFFFFFFFull;
    if (tid < KCB)   g_counts[tid] = 0.0f;
    if (tid == 0)    g_lossAcc = 0.0f;

    if (tid < KCB) {
        const float4* r = (const float4*)(w + (size_t)tid * DDIM);
        float s = 0.0f;
        for (int j = 0; j < DDIM / 4; j++) {
            float4 v = r[j];
            s = __fadd_rn(s, __fmul_rn(v.x, v.x));
            s = __fadd_rn(s, __fmul_rn(v.y, v.y));
            s = __fadd_rn(s, __fmul_rn(v.z, v.z));
            s = __fadd_rn(s, __fmul_rn(v.w, v.w));
        }
        g_E2[tid] = s;
    }
    if (tid < N_TOK) {
        const float4* r = (const float4*)(z + (size_t)tid * DDIM);
        float s = 0.0f;
        for (int j = 0; j < DDIM / 4; j++) {
            float4 v = r[j];
            s = __fadd_rn(s, __fmul_rn(v.x, v.x));
            s = __fadd_rn(s, __fmul_rn(v.y, v.y));
            s = __fadd_rn(s, __fmul_rn(v.z, v.z));
            s = __fadd_rn(s, __fmul_rn(v.w, v.w));
        }
        g_S[tid] = s;
    }
}

// ============================================================
// GEMM (ascending-d fused-FMA accumulators, matching Eigen/cublas)
// + fused argmin of dist = fl(fl(S - 2*dot) + E)  (reference rounding)
// block: 128 rows x 128 codes, 8 code-tiles/block; grid (128, 8)
// 256 threads, thread tile 8x8, accumulators packed f32x2 (row pairs)
// ============================================================
__device__ __forceinline__ void store_tile(float* A, float* B, int q4, int rowL,
                                           float4 a0, float4 a1, float4 b0, float4 b1) {
    A[(q4 + 0) * SS + rowL] = a0.x; A[(q4 + 1) * SS + rowL] = a0.y;
    A[(q4 + 2) * SS + rowL] = a0.z; A[(q4 + 3) * SS + rowL] = a0.w;
    A[(q4 + 0) * SS + rowL + 64] = a1.x; A[(q4 + 1) * SS + rowL + 64] = a1.y;
    A[(q4 + 2) * SS + rowL + 64] = a1.z; A[(q4 + 3) * SS + rowL + 64] = a1.w;
    B[(q4 + 0) * SS + rowL] = b0.x; B[(q4 + 1) * SS + rowL] = b0.y;
    B[(q4 + 2) * SS + rowL] = b0.z; B[(q4 + 3) * SS + rowL] = b0.w;
    B[(q4 + 0) * SS + rowL + 64] = b1.x; B[(q4 + 1) * SS + rowL + 64] = b1.y;
    B[(q4 + 2) * SS + rowL + 64] = b1.z; B[(q4 + 3) * SS + rowL + 64] = b1.w;
}

__global__ __launch_bounds__(256) void k_gemm(const float* __restrict__ z,
                                              const float* __restrict__ w) {
    __shared__ union {
        float ab[2][2][16 * SS];           // [buf][A=0/B=1][16 d x 132]
        unsigned long long red[128 * 17];  // argmin cross-thread reduce
    } sm;

    const int t = threadIdx.x;
    const int m0 = blockIdx.x * 128;
    const int kbase = blockIdx.y * 1024;
    const int rowB = (t >> 4) << 3;   // 0..120
    const int colB = (t & 15) << 3;   // 0..120
    const int rowL = t >> 2;          // loader row 0..63 (+64 for 2nd)
    const int q4 = (t & 3) << 2;      // loader d offset 0,4,8,12

    float bestD[8];
    int bestK[8];
    float Srow[8];
#pragma unroll
    for (int i = 0; i < 8; i++) {
        bestD[i] = 3.4028235e38f;
        bestK[i] = 0;
        Srow[i] = __ldg(&g_S[m0 + rowB + i]);
    }

    const float* zb = z + (size_t)(m0 + rowL) * DDIM + q4;

    for (int kt = 0; kt < 8; kt++) {
        const int k0 = kbase + kt * 128;
        const float* wb = w + (size_t)(k0 + rowL) * DDIM + q4;

        unsigned long long acc[4][8];
#pragma unroll
        for (int p = 0; p < 4; p++)
#pragma unroll
            for (int j = 0; j < 8; j++) acc[p][j] = 0ull;

        float4 rA0 = *(const float4*)(zb);
        float4 rA1 = *(const float4*)(zb + 64 * DDIM);
        float4 rB0 = *(const float4*)(wb);
        float4 rB1 = *(const float4*)(wb + 64 * DDIM);
        __syncthreads();
        store_tile(sm.ab[0][0], sm.ab[0][1], q4, rowL, rA0, rA1, rB0, rB1);
        __syncthreads();

        int cur = 0;
#pragma unroll 1
        for (int dt = 0; dt < 16; dt++) {
            if (dt < 15) {
                const float* zp = zb + (dt + 1) * 16;
                const float* wp = wb + (dt + 1) * 16;
                rA0 = *(const float4*)(zp);
                rA1 = *(const float4*)(zp + 64 * DDIM);
                rB0 = *(const float4*)(wp);
                rB1 = *(const float4*)(wp + 64 * DDIM);
            }
            const float* A = sm.ab[cur][0];
            const float* B = sm.ab[cur][1];
#pragma unroll
            for (int d = 0; d < 16; d++) {
                ulonglong2 a01 = *(const ulonglong2*)(A + d * SS + rowB);
                ulonglong2 a23 = *(const ulonglong2*)(A + d * SS + rowB + 4);
                float4 b0 = *(const float4*)(B + d * SS + colB);
                float4 b1 = *(const float4*)(B + d * SS + colB + 4);
                unsigned long long ap[4] = {a01.x, a01.y, a23.x, a23.y};
                float bv[8] = {b0.x, b0.y, b0.z, b0.w, b1.x, b1.y, b1.z, b1.w};
                unsigned long long bb[8];
#pragma unroll
                for (int j = 0; j < 8; j++)
                    asm("mov.b64 %0, {%1, %1};" : "=l"(bb[j]) : "f"(bv[j]));
#pragma unroll
                for (int p = 0; p < 4; p++)
#pragma unroll
                    for (int j = 0; j < 8; j++)
                        asm("fma.rn.f32x2 %0, %1, %2, %0;"
                            : "+l"(acc[p][j]) : "l"(ap[p]), "l"(bb[j]));
            }
            if (dt < 15) {
                int nb = cur ^ 1;
                store_tile(sm.ab[nb][0], sm.ab[nb][1], q4, rowL, rA0, rA1, rB0, rB1);
                __syncthreads();
                cur = nb;
            }
        }

        // epilogue: dist = fl(fl(S - 2*dot) + E), running first-min (k ascending)
#pragma unroll
        for (int j = 0; j < 8; j++) {
            int kk = k0 + colB + j;
            float Ek = __ldg(&g_E2[kk]);
#pragma unroll
            for (int p = 0; p < 4; p++) {
                float d0, d1;
                asm("mov.b64 {%0, %1}, %2;" : "=f"(d0), "=f"(d1) : "l"(acc[p][j]));
                float t0 = __fadd_rn(__fadd_rn(Srow[2 * p],     -2.0f * d0), Ek);
                float t1 = __fadd_rn(__fadd_rn(Srow[2 * p + 1], -2.0f * d1), Ek);
                if (t0 < bestD[2 * p])     { bestD[2 * p] = t0;     bestK[2 * p] = kk; }
                if (t1 < bestD[2 * p + 1]) { bestD[2 * p + 1] = t1; bestK[2 * p + 1] = kk; }
            }
        }
    }

    __syncthreads();  // done with ab; reuse as red
#pragma unroll
    for (int i = 0; i < 8; i++) {
        unsigned b = __float_as_uint(bestD[i]);
        unsigned u = (b & 0x80000000u) ? ~b : (b | 0x80000000u);  // ascending map
        unsigned long long key = ((unsigned long long)u << 32) | (unsigned)bestK[i];
        sm.red[(rowB + i) * 17 + (t & 15)] = key;
    }
    __syncthreads();
    if (t < 128) {
        unsigned long long mn = sm.red[t * 17];
#pragma unroll
        for (int c = 1; c < 16; c++) {
            unsigned long long v = sm.red[t * 17 + c];
            if (v < mn) mn = v;
        }
        atomicMin(&g_best[m0 + t], mn);
    }
}

// ============================================================
// assign: warp per token — decode idx, gather code, write
// quantized_st = fl(z + fl(q - z)) (reference fp order, no contraction),
// loss partial, counts / dw accumulation
// ============================================================
__global__ void k_assign(const float* __restrict__ z, const float* __restrict__ w,
                         float* __restrict__ out) {
    int gw = (blockIdx.x * blockDim.x + threadIdx.x) >> 5;
    int lane = threadIdx.x & 31;
    if (gw >= N_TOK) return;
    int idx = (int)(unsigned)(g_best[gw] & 0xFFFFFFFFull);

    const float4* wr = (const float4*)(w + (size_t)idx * DDIM);
    const float4* zr = (const float4*)(z + (size_t)gw * DDIM);
    float4* qr = (float4*)(out + O_QUANT + (size_t)gw * DDIM);
    float se = 0.0f;
#pragma unroll
    for (int j = lane; j < DDIM / 4; j += 32) {
        float4 qv = wr[j];
        float4 zv = zr[j];
        float dx = __fsub_rn(qv.x, zv.x), dy = __fsub_rn(qv.y, zv.y);
        float dz2 = __fsub_rn(qv.z, zv.z), dw2 = __fsub_rn(qv.w, zv.w);
        se += dx * dx + dy * dy + dz2 * dz2 + dw2 * dw2;
        float4 o;
        o.x = __fadd_rn(zv.x, dx); o.y = __fadd_rn(zv.y, dy);
        o.z = __fadd_rn(zv.z, dz2); o.w = __fadd_rn(zv.w, dw2);
        qr[j] = o;
        float* dwp = &g_dw[(size_t)idx * DDIM + j * 4];
        atomicAdd(dwp + 0, zv.x); atomicAdd(dwp + 1, zv.y);
        atomicAdd(dwp + 2, zv.z); atomicAdd(dwp + 3, zv.w);
    }
    for (int o = 16; o; o >>= 1) se += __shfl_xor_sync(0xffffffffu, se, o);
    if (lane == 0) {
        atomicAdd(&g_lossAcc, se);
        atomicAdd(&g_counts[idx], 1.0f);
        out[O_IDX + gw] = (float)idx;
    }
}

// ============================================================
// EMA updates
// ============================================================
__global__ void k_ema(const float* __restrict__ ecs, const float* __restrict__ emaw,
                      float* __restrict__ out) {
    int i = blockIdx.x * 256 + threadIdx.x;
    if (i < KCB * DDIM) out[O_EMAW + i] = 0.99f * emaw[i] + 0.01f * g_dw[i];
    if (i < KCB) {
        float v = 0.99f * ecs[i] + 0.01f * g_counts[i];
        g_ncs[i] = v;
        out[O_CS + i] = v;
    }
}

// single block: deterministic n = sum(ncs); finalize loss
__global__ void k_finalize(float* __restrict__ out) {
    __shared__ float sh[1024];
    int t = threadIdx.x;
    float s = 0.0f;
    for (int i = t; i < KCB; i += 1024) s += g_ncs[i];
    sh[t] = s;
    __syncthreads();
    for (int o = 512; o > 0; o >>= 1) {
        if (t < o) sh[t] += sh[t + o];
        __syncthreads();
    }
    if (t == 0) {
        g_n = sh[0];
        float m = g_lossAcc / (float)(N_TOK * DDIM);
        out[O_LOSS] = __fadd_rn(m, __fmul_rn(0.25f, m));
    }
}

__global__ void k_weight(float* __restrict__ out) {
    int i = blockIdx.x * 256 + threadIdx.x;
    if (i >= KCB * DDIM) return;
    int k = i >> 8;
    float n = g_n;
    float cs = (g_ncs[k] + 1e-5f) / (n + (float)KCB * 1e-5f) * n;
    out[O_W + i] = out[O_EMAW + i] / cs;
}

// ============================================================
extern "C" void kernel_launch(void* const* d_in, const int* in_sizes, int n_in,
                              void* d_out, int out_size) {
    const float* z    = (const float*)d_in[0];   // [16,1024,256]
    const float* w    = (const float*)d_in[1];   // [8192,256]
    const float* ecs  = (const float*)d_in[2];   // [8192]
    const float* emaw = (const float*)d_in[3];   // [8192,256]
    float* out = (float*)d_out;

    k_prep<<<1024, 256>>>(z, w);
    dim3 g(N_TOK / 128, KCB / 1024);
    k_gemm<<<g, 256>>>(z, w);
    k_assign<<<(N_TOK * 32) / 256, 256>>>(z, w, out);
    k_ema<<<(KCB * DDIM) / 256, 256>>>(ecs, emaw, out);
    k_finalize<<<1, 1024>>>(out);
    k_weight<<<(KCB * DDIM) / 256, 256>>>(out);
}

// round 7
// speedup vs baseline: 1.1863x; 1.1863x over previous
#include <cuda_runtime.h>

#define N_TOK 16384
#define KCB   8192
#define DDIM  256
#define BM    256   // gemm block rows
#define BN    128   // gemm block cols

// ---- output layout (float32, reference return order, flattened) ----
#define O_QUANT 0
#define O_LOSS  4194304
#define O_IDX   4194305
#define O_W     4210689
#define O_CS    6307841
#define O_EMAW  6316033

// ---- scratch (__device__ globals: no allocation allowed) ----
__device__ float              g_E2[KCB];     // sum(w_k^2), reference order
__device__ float              g_S[N_TOK];    // sum(x_i^2), reference order
__device__ unsigned long long g_best[N_TOK];
__device__ float              g_counts[KCB];
__device__ float              g_dw[KCB * DDIM];
__device__ float              g_lossAcc;
__device__ float              g_ncs[KCB];
__device__ float              g_n;

// ============================================================
// prep: zero scratch; S_i and E_k as STRICT sequential unfused
// fp32 sums (replicates reference reduction rounding — do not touch)
// ============================================================
__global__ void k_prep(const float* __restrict__ z, const float* __restrict__ w) {
    int tid = blockIdx.x * 256 + threadIdx.x;
    int T = gridDim.x * 256;
    for (int i = tid; i < KCB * DDIM; i += T) g_dw[i] = 0.0f;
    if (tid < N_TOK) g_best[tid] = 0xFFFFFFFFFFFFFFFFull;
    if (tid < KCB)   g_counts[tid] = 0.0f;
    if (tid == 0)    g_lossAcc = 0.0f;

    if (tid < KCB) {
        const float4* r = (const float4*)(w + (size_t)tid * DDIM);
        float s = 0.0f;
        for (int j = 0; j < DDIM / 4; j++) {
            float4 v = r[j];
            s = __fadd_rn(s, __fmul_rn(v.x, v.x));
            s = __fadd_rn(s, __fmul_rn(v.y, v.y));
            s = __fadd_rn(s, __fmul_rn(v.z, v.z));
            s = __fadd_rn(s, __fmul_rn(v.w, v.w));
        }
        g_E2[tid] = s;
    }
    if (tid < N_TOK) {
        const float4* r = (const float4*)(z + (size_t)tid * DDIM);
        float s = 0.0f;
        for (int j = 0; j < DDIM / 4; j++) {
            float4 v = r[j];
            s = __fadd_rn(s, __fmul_rn(v.x, v.x));
            s = __fadd_rn(s, __fmul_rn(v.y, v.y));
            s = __fadd_rn(s, __fmul_rn(v.z, v.z));
            s = __fadd_rn(s, __fmul_rn(v.w, v.w));
        }
        g_S[tid] = s;
    }
}

// ============================================================
// GEMM (ascending-d fused-FMA accumulators, bit-matching reference)
// + fused argmin of dist = fl(fl(S - 2*dot) + E)
// block tile 256 rows x 128 codes, 4 code-tiles/block; grid (64, 16)
// 256 threads, thread tile 16x8, accumulators packed f32x2 (row pairs)
// B columns split {4c..4c+3, 64+4c..4c+3} -> conflict-free LDS
// ============================================================
__device__ __forceinline__ void st_stage(float* A, float* B, int q4, int rowL,
                                         const float4* ra, const float4* rb) {
#pragma unroll
    for (int r = 0; r < 4; r++) {
        A[(q4 + 0) * BM + rowL + r * 64] = ra[r].x;
        A[(q4 + 1) * BM + rowL + r * 64] = ra[r].y;
        A[(q4 + 2) * BM + rowL + r * 64] = ra[r].z;
        A[(q4 + 3) * BM + rowL + r * 64] = ra[r].w;
    }
#pragma unroll
    for (int r = 0; r < 2; r++) {
        B[(q4 + 0) * BN + rowL + r * 64] = rb[r].x;
        B[(q4 + 1) * BN + rowL + r * 64] = rb[r].y;
        B[(q4 + 2) * BN + rowL + r * 64] = rb[r].z;
        B[(q4 + 3) * BN + rowL + r * 64] = rb[r].w;
    }
}

__global__ __launch_bounds__(256) void k_gemm(const float* __restrict__ z,
                                              const float* __restrict__ w) {
    __shared__ union {
        struct { float A[2][16 * BM]; float B[2][16 * BN]; } s;  // 48 KB exactly
        unsigned long long red[256 * 17];                         // argmin reduce
    } sm;

    const int t = threadIdx.x;
    const int m0 = blockIdx.x * BM;
    const int kbase = blockIdx.y * 512;      // 4 code tiles of 128
    const int tc = t & 15;
    const int rowB = (t >> 4) << 4;          // 0..240, 16 rows per thread
    const int c0 = tc * 4;                   // cols c0..c0+3
    const int c1 = 64 + tc * 4;              // cols c1..c1+3
    const int rowL = t >> 2;                 // loader row 0..63
    const int q4 = (t & 3) << 2;             // loader d offset 0,4,8,12

    float bestD[16];
    int bestK[16];
#pragma unroll
    for (int i = 0; i < 16; i++) { bestD[i] = 3.4028235e38f; bestK[i] = 0; }

    const float* zb = z + (size_t)(m0 + rowL) * DDIM + q4;

    for (int kt = 0; kt < 4; kt++) {
        const int k0 = kbase + kt * 128;
        const float* wb = w + (size_t)(k0 + rowL) * DDIM + q4;

        unsigned long long acc[8][8];
#pragma unroll
        for (int p = 0; p < 8; p++)
#pragma unroll
            for (int j = 0; j < 8; j++) acc[p][j] = 0ull;

        float4 ra[4], rb[2];
#pragma unroll
        for (int r = 0; r < 4; r++) ra[r] = *(const float4*)(zb + r * 64 * DDIM);
#pragma unroll
        for (int r = 0; r < 2; r++) rb[r] = *(const float4*)(wb + r * 64 * DDIM);
        __syncthreads();
        st_stage(sm.s.A[0], sm.s.B[0], q4, rowL, ra, rb);
        __syncthreads();

        int cur = 0;
#pragma unroll 1
        for (int dt = 0; dt < 16; dt++) {
            if (dt < 15) {
                const int doff = (dt + 1) * 16;
#pragma unroll
                for (int r = 0; r < 4; r++)
                    ra[r] = *(const float4*)(zb + r * 64 * DDIM + doff);
#pragma unroll
                for (int r = 0; r < 2; r++)
                    rb[r] = *(const float4*)(wb + r * 64 * DDIM + doff);
            }
            const float* A = sm.s.A[cur];
            const float* Bp = sm.s.B[cur];
#pragma unroll
            for (int d = 0; d < 16; d++) {
                ulonglong2 a01 = *(const ulonglong2*)(A + d * BM + rowB);
                ulonglong2 a23 = *(const ulonglong2*)(A + d * BM + rowB + 4);
                ulonglong2 a45 = *(const ulonglong2*)(A + d * BM + rowB + 8);
                ulonglong2 a67 = *(const ulonglong2*)(A + d * BM + rowB + 12);
                float4 b0 = *(const float4*)(Bp + d * BN + c0);
                float4 b1 = *(const float4*)(Bp + d * BN + c1);
                unsigned long long ap[8] = {a01.x, a01.y, a23.x, a23.y,
                                            a45.x, a45.y, a67.x, a67.y};
                float bv[8] = {b0.x, b0.y, b0.z, b0.w, b1.x, b1.y, b1.z, b1.w};
                unsigned long long bb[8];
#pragma unroll
                for (int j = 0; j < 8; j++)
                    asm("mov.b64 %0, {%1, %1};" : "=l"(bb[j]) : "f"(bv[j]));
#pragma unroll
                for (int p = 0; p < 8; p++)
#pragma unroll
                    for (int j = 0; j < 8; j++)
                        asm("fma.rn.f32x2 %0, %1, %2, %0;"
                            : "+l"(acc[p][j]) : "l"(ap[p]), "l"(bb[j]));
            }
            if (dt < 15) {
                int nb = cur ^ 1;
                st_stage(sm.s.A[nb], sm.s.B[nb], q4, rowL, ra, rb);
                __syncthreads();
                cur = nb;
            }
        }

        // epilogue: dist = fl(fl(S - 2*dot) + E), running first-min (k ascending)
        float Sl[16];
#pragma unroll
        for (int i = 0; i < 16; i++) Sl[i] = __ldg(&g_S[m0 + rowB + i]);
#pragma unroll
        for (int j = 0; j < 8; j++) {
            const int kk = k0 + ((j < 4) ? (c0 + j) : (c1 + j - 4));
            const float Ek = __ldg(&g_E2[kk]);
#pragma unroll
            for (int p = 0; p < 8; p++) {
                float d0, d1;
                asm("mov.b64 {%0, %1}, %2;" : "=f"(d0), "=f"(d1) : "l"(acc[p][j]));
                float t0 = __fadd_rn(__fadd_rn(Sl[2 * p],     -2.0f * d0), Ek);
                float t1 = __fadd_rn(__fadd_rn(Sl[2 * p + 1], -2.0f * d1), Ek);
                if (t0 < bestD[2 * p])     { bestD[2 * p] = t0;     bestK[2 * p] = kk; }
                if (t1 < bestD[2 * p + 1]) { bestD[2 * p + 1] = t1; bestK[2 * p + 1] = kk; }
            }
        }
    }

    __syncthreads();  // done with buffers; reuse as red
#pragma unroll
    for (int i = 0; i < 16; i++) {
        unsigned b = __float_as_uint(bestD[i]);
        unsigned u = (b & 0x80000000u) ? ~b : (b | 0x80000000u);  // ascending map
        unsigned long long key = ((unsigned long long)u << 32) | (unsigned)bestK[i];
        sm.red[(rowB + i) * 17 + tc] = key;
    }
    __syncthreads();
    {
        unsigned long long mn = sm.red[t * 17];
#pragma unroll
        for (int c = 1; c < 16; c++) {
            unsigned long long v = sm.red[t * 17 + c];
            if (v < mn) mn = v;
        }
        atomicMin(&g_best[m0 + t], mn);
    }
}

// ============================================================
// assign: warp per token — decode idx, gather code, write
// quantized_st = fl(z + fl(q - z)) (reference fp order, no contraction),
// loss partial, counts / dw accumulation
// ============================================================
__global__ void k_assign(const float* __restrict__ z, const float* __restrict__ w,
                         float* __restrict__ out) {
    int gw = (blockIdx.x * blockDim.x + threadIdx.x) >> 5;
    int lane = threadIdx.x & 31;
    if (gw >= N_TOK) return;
    int idx = (int)(unsigned)(g_best[gw] & 0xFFFFFFFFull);

    const float4* wr = (const float4*)(w + (size_t)idx * DDIM);
    const float4* zr = (const float4*)(z + (size_t)gw * DDIM);
    float4* qr = (float4*)(out + O_QUANT + (size_t)gw * DDIM);
    float se = 0.0f;
#pragma unroll
    for (int j = lane; j < DDIM / 4; j += 32) {
        float4 qv = wr[j];
        float4 zv = zr[j];
        float dx = __fsub_rn(qv.x, zv.x), dy = __fsub_rn(qv.y, zv.y);
        float dz2 = __fsub_rn(qv.z, zv.z), dw2 = __fsub_rn(qv.w, zv.w);
        se += dx * dx + dy * dy + dz2 * dz2 + dw2 * dw2;
        float4 o;
        o.x = __fadd_rn(zv.x, dx); o.y = __fadd_rn(zv.y, dy);
        o.z = __fadd_rn(zv.z, dz2); o.w = __fadd_rn(zv.w, dw2);
        qr[j] = o;
        float* dwp = &g_dw[(size_t)idx * DDIM + j * 4];
        atomicAdd(dwp + 0, zv.x); atomicAdd(dwp + 1, zv.y);
        atomicAdd(dwp + 2, zv.z); atomicAdd(dwp + 3, zv.w);
    }
    for (int o = 16; o; o >>= 1) se += __shfl_xor_sync(0xffffffffu, se, o);
    if (lane == 0) {
        atomicAdd(&g_lossAcc, se);
        atomicAdd(&g_counts[idx], 1.0f);
        out[O_IDX + gw] = (float)idx;
    }
}

// ============================================================
// EMA updates
// ============================================================
__global__ void k_ema(const float* __restrict__ ecs, const float* __restrict__ emaw,
                      float* __restrict__ out) {
    int i = blockIdx.x * 256 + threadIdx.x;
    if (i < KCB * DDIM) out[O_EMAW + i] = 0.99f * emaw[i] + 0.01f * g_dw[i];
    if (i < KCB) {
        float v = 0.99f * ecs[i] + 0.01f * g_counts[i];
        g_ncs[i] = v;
        out[O_CS + i] = v;
    }
}

// single block: deterministic n = sum(ncs); finalize loss
__global__ void k_finalize(float* __restrict__ out) {
    __shared__ float sh[1024];
    int t = threadIdx.x;
    float s = 0.0f;
    for (int i = t; i < KCB; i += 1024) s += g_ncs[i];
    sh[t] = s;
    __syncthreads();
    for (int o = 512; o > 0; o >>= 1) {
        if (t < o) sh[t] += sh[t + o];
        __syncthreads();
    }
    if (t == 0) {
        g_n = sh[0];
        float m = g_lossAcc / (float)(N_TOK * DDIM);
        out[O_LOSS] = __fadd_rn(m, __fmul_rn(0.25f, m));
    }
}

__global__ void k_weight(float* __restrict__ out) {
    int i = blockIdx.x * 256 + threadIdx.x;
    if (i >= KCB * DDIM) return;
    int k = i >> 8;
    float n = g_n;
    float cs = (g_ncs[k] + 1e-5f) / (n + (float)KCB * 1e-5f) * n;
    out[O_W + i] = out[O_EMAW + i] / cs;
}

// ============================================================
extern "C" void kernel_launch(void* const* d_in, const int* in_sizes, int n_in,
                              void* d_out, int out_size) {
    const float* z    = (const float*)d_in[0];   // [16,1024,256]
    const float* w    = (const float*)d_in[1];   // [8192,256]
    const float* ecs  = (const float*)d_in[2];   // [8192]
    const float* emaw = (const float*)d_in[3];   // [8192,256]
    float* out = (float*)d_out;

    k_prep<<<1024, 256>>>(z, w);
    dim3 g(N_TOK / BM, 16);
    k_gemm<<<g, 256>>>(z, w);
    k_assign<<<(N_TOK * 32) / 256, 256>>>(z, w, out);
    k_ema<<<(KCB * DDIM) / 256, 256>>>(ecs, emaw, out);
    k_finalize<<<1, 1024>>>(out);
    k_weight<<<(KCB * DDIM) / 256, 256>>>(out);
}